// round 2
// baseline (speedup 1.0000x reference)
#include <cuda_runtime.h>
#include <cstdint>

// Problem constants
#define N_IN   1000
#define N_H    3000
#define N_OUT  10
#define N_TOT  4010              // N_IN + N_H + N_OUT
#define L_TOT  3010              // N_H + N_OUT
#define TAU    10
#define KLEN   16040             // N_TOT * A * B_FF  (GEMV reduction length)
#define KV4    4010              // KLEN / 4
#define ROWS   6020              // L_TOT * A

// Threefry variant: 1 = jax_threefry_partitionable (modern JAX default),
//                   0 = legacy concat-halves scheme (fallback if flips seen)
#define PARTITIONABLE 1

// Device scratch (no allocations allowed)
__device__ __align__(16) float g_tr_ff[KLEN];
__device__ __align__(16) float g_tr_fb[KLEN];
__device__ float g_pot[ROWS];

// ---------------------------------------------------------------------------
// K1: ff_tr[n,a,b] = sum_t hist[n,a,TAU-1-t] * filt[b,t]   (both filters)
// Flat index i = n*4 + a*2 + b  (matches ff_weights' (n,b,k) contraction layout)
// ---------------------------------------------------------------------------
__global__ void k_transform(const float* __restrict__ hist,
                            const float* __restrict__ ff_f,
                            const float* __restrict__ fb_f) {
    int i = blockIdx.x * blockDim.x + threadIdx.x;
    if (i >= KLEN) return;
    int b  = i & 1;
    int na = i >> 1;                      // n*2 + a
    const float* h = hist + na * TAU;
    float sff = 0.f, sfb = 0.f;
#pragma unroll
    for (int t = 0; t < TAU; t++) {
        float s = h[TAU - 1 - t];
        sff += s * ff_f[b * TAU + t];
        sfb += s * fb_f[b * TAU + t];
    }
    g_tr_ff[i] = sff;
    g_tr_fb[i] = sfb;
}

// ---------------------------------------------------------------------------
// K2: the 386MB GEMV.  4 rows per CTA, 128 threads per row, vector in SMEM.
// Epilogue fuses fb_pot + bias (TEMPERATURE = 1).
// ---------------------------------------------------------------------------
__global__ void __launch_bounds__(512, 1)
k_gemv(const float* __restrict__ W,
       const float* __restrict__ fb_w,
       const float* __restrict__ bias) {
    extern __shared__ float4 sv[];       // KV4 float4 = 64160 B
    __shared__ float red[4][4];          // [local row][warp-of-row]

    int tid = threadIdx.x;
    const float4* v4 = reinterpret_cast<const float4*>(g_tr_ff);
    for (int i = tid; i < KV4; i += 512) sv[i] = v4[i];
    __syncthreads();

    int rl   = tid >> 7;                 // 0..3 local row
    int lane = tid & 127;                // 0..127 within row
    int row  = (blockIdx.x << 2) + rl;   // grid = ROWS/4 exactly

    const float4* w4 = reinterpret_cast<const float4*>(W) + (size_t)row * KV4;
    float acc = 0.f;
#pragma unroll 4
    for (int i = lane; i < KV4; i += 128) {
        float4 w = __ldg(w4 + i);
        float4 v = sv[i];
        acc += w.x * v.x + w.y * v.y + w.z * v.z + w.w * v.w;
    }
#pragma unroll
    for (int o = 16; o > 0; o >>= 1)
        acc += __shfl_down_sync(0xffffffffu, acc, o);
    if ((lane & 31) == 0) red[rl][lane >> 5] = acc;
    __syncthreads();

    if (lane == 0) {
        float s = red[rl][0] + red[rl][1] + red[rl][2] + red[rl][3];
        int fbb = (N_IN * 2 + row) * 2;               // fb_tr[N_IN+j, a, k] flat
        float fbp = fb_w[row * 2]     * g_tr_fb[fbb]
                  + fb_w[row * 2 + 1] * g_tr_fb[fbb + 1];
        g_pot[row] = s + fbp + bias[row];             // /TEMPERATURE (=1)
    }
}

// ---------------------------------------------------------------------------
// Threefry2x32, key = jax.random.key(1) -> (k0,k1) = (0,1)
// ---------------------------------------------------------------------------
__device__ __forceinline__ uint32_t rotl32(uint32_t v, int d) {
    return (v << d) | (v >> (32 - d));
}

__device__ __forceinline__ void threefry2x32_01(uint32_t c0, uint32_t c1,
                                                uint32_t& o0, uint32_t& o1) {
    const uint32_t k0 = 0u, k1 = 1u;
    const uint32_t k2 = k0 ^ k1 ^ 0x1BD11BDAu;
    uint32_t x0 = c0 + k0, x1 = c1 + k1;
#define TF_RND(r) { x0 += x1; x1 = rotl32(x1, (r)) ^ x0; }
    TF_RND(13) TF_RND(15) TF_RND(26) TF_RND(6)   x0 += k1; x1 += k2 + 1u;
    TF_RND(17) TF_RND(29) TF_RND(16) TF_RND(24)  x0 += k2; x1 += k0 + 2u;
    TF_RND(13) TF_RND(15) TF_RND(26) TF_RND(6)   x0 += k0; x1 += k1 + 3u;
    TF_RND(17) TF_RND(29) TF_RND(16) TF_RND(24)  x0 += k1; x1 += k2 + 4u;
    TF_RND(13) TF_RND(15) TF_RND(26) TF_RND(6)   x0 += k2; x1 += k0 + 5u;
#undef TF_RND
    o0 = x0; o1 = x1;
}

// gumbel sample at flat index f of a 9000-element draw (shape (3000,3))
__device__ float gumbel_at(uint32_t f) {
    uint32_t bits;
#if PARTITIONABLE
    uint32_t o0, o1;
    threefry2x32_01(0u, f, o0, o1);       // counts = 64-bit flat index (hi=0, lo=f)
    bits = o0 ^ o1;                       // 32-bit fold
#else
    // legacy: counts = iota(9000) split into halves (x0=i, x1=i+4500)
    const uint32_t half = 4500u;
    uint32_t i = (f < half) ? f : (f - half);
    uint32_t o0, o1;
    threefry2x32_01(i, i + half, o0, o1);
    bits = (f < half) ? o0 : o1;
#endif
    float uf = __uint_as_float((bits >> 9) | 0x3f800000u) - 1.0f;   // [0,1)
    const float tiny = 1.1754943508222875e-38f;
    if (uf < tiny) uf = tiny;             // uniform(minval=tiny, maxval=1)
    return (float)(-log(-log((double)uf)));
}

// ---------------------------------------------------------------------------
// K3: gumbel-argmax spikes (j < N_H) / input spikes (j >= N_H), log-softmax,
// coef dot -> log_proba[j]
// ---------------------------------------------------------------------------
__global__ void k_final(const float* __restrict__ input_signal,
                        float* __restrict__ out) {
    int j = blockIdx.x * blockDim.x + threadIdx.x;
    if (j >= L_TOT) return;

    float p0 = g_pot[2 * j], p1 = g_pot[2 * j + 1];
    float s0, s1;
    if (j < N_H) {
        float z0 =      gumbel_at(3u * (uint32_t)j);
        float z1 = p0 + gumbel_at(3u * (uint32_t)j + 1u);
        float z2 = p1 + gumbel_at(3u * (uint32_t)j + 2u);
        int best = 0; float bv = z0;
        if (z1 > bv) { bv = z1; best = 1; }
        if (z2 > bv) {          best = 2; }
        s0 = (best == 1) ? 1.f : 0.f;
        s1 = (best == 2) ? 1.f : 0.f;
    } else {
        int r = N_IN + (j - N_H);                   // input_signal[N_IN:]
        s0 = input_signal[r * 2];
        s1 = input_signal[r * 2 + 1];
    }

    float m   = fmaxf(0.f, fmaxf(p0, p1));
    float lse = m + logf(expf(-m) + expf(p0 - m) + expf(p1 - m));
    out[j] = (1.f - s0 - s1) * (-lse) + s0 * (p0 - lse) + s1 * (p1 - lse);
}

// ---------------------------------------------------------------------------
extern "C" void kernel_launch(void* const* d_in, const int* in_sizes, int n_in,
                              void* d_out, int out_size) {
    const float* input_signal = (const float*)d_in[0];
    const float* hist         = (const float*)d_in[1];
    const float* ff_w         = (const float*)d_in[2];
    const float* fb_w         = (const float*)d_in[3];
    const float* bias         = (const float*)d_in[4];
    const float* ff_f         = (const float*)d_in[5];
    const float* fb_f         = (const float*)d_in[6];
    float* out = (float*)d_out;

    (void)in_sizes; (void)n_in; (void)out_size;

    cudaFuncSetAttribute(k_gemv, cudaFuncAttributeMaxDynamicSharedMemorySize,
                         KV4 * 16 + 64);

    k_transform<<<(KLEN + 255) / 256, 256>>>(hist, ff_f, fb_f);
    k_gemv<<<ROWS / 4, 512, KV4 * 16>>>(ff_w, fb_w, bias);
    k_final<<<(L_TOT + 255) / 256, 256>>>(input_signal, out);
}

// round 4
// speedup vs baseline: 1.0164x; 1.0164x over previous
#include <cuda_runtime.h>
#include <cstdint>

// Problem constants
#define N_IN   1000
#define N_H    3000
#define N_OUT  10
#define N_TOT  4010              // N_IN + N_H + N_OUT
#define L_TOT  3010              // N_H + N_OUT  (== number of output elements / row-pairs)
#define TAU    10
#define KLEN   16040             // N_TOT * A * B_FF  (GEMV reduction length)
#define KV4    4010              // KLEN / 4
#define ROWS   6020              // L_TOT * A
#define GRID   296               // 2 persistent CTAs per SM on 148 SMs

// ---------------------------------------------------------------------------
// Threefry2x32, key = jax.random.key(1) -> (k0,k1) = (0,1)
// (jax_threefry_partitionable path, verified rel_err 1.5e-7 in R2)
// ---------------------------------------------------------------------------
__device__ __forceinline__ uint32_t rotl32(uint32_t v, int d) {
    return (v << d) | (v >> (32 - d));
}

__device__ __forceinline__ void threefry2x32_01(uint32_t c0, uint32_t c1,
                                                uint32_t& o0, uint32_t& o1) {
    const uint32_t k0 = 0u, k1 = 1u;
    const uint32_t k2 = k0 ^ k1 ^ 0x1BD11BDAu;
    uint32_t x0 = c0 + k0, x1 = c1 + k1;
#define TF_RND(r) { x0 += x1; x1 = rotl32(x1, (r)) ^ x0; }
    TF_RND(13) TF_RND(15) TF_RND(26) TF_RND(6)   x0 += k1; x1 += k2 + 1u;
    TF_RND(17) TF_RND(29) TF_RND(16) TF_RND(24)  x0 += k2; x1 += k0 + 2u;
    TF_RND(13) TF_RND(15) TF_RND(26) TF_RND(6)   x0 += k0; x1 += k1 + 3u;
    TF_RND(17) TF_RND(29) TF_RND(16) TF_RND(24)  x0 += k1; x1 += k2 + 4u;
    TF_RND(13) TF_RND(15) TF_RND(26) TF_RND(6)   x0 += k2; x1 += k0 + 5u;
#undef TF_RND
    o0 = x0; o1 = x1;
}

// gumbel sample at flat index f of the (3000,3) categorical draw
__device__ __forceinline__ float gumbel_at(uint32_t f) {
    uint32_t o0, o1;
    threefry2x32_01(0u, f, o0, o1);       // counts = (hi=0, lo=f)
    uint32_t bits = o0 ^ o1;              // 32-bit fold (partitionable)
    float uf = __uint_as_float((bits >> 9) | 0x3f800000u) - 1.0f;   // [0,1)
    const float tiny = 1.1754943508222875e-38f;
    if (uf < tiny) uf = tiny;
    return (float)(-log(-log((double)uf)));
}

// ---------------------------------------------------------------------------
// Single fused persistent kernel.
//  Prologue: ff transform -> smem vector (16040 floats)
//  Loop over row-pairs p = bid + GRID*k:
//    rows 2p (threads 0-255) and 2p+1 (threads 256-511) each dot the
//    64KB weight row against the smem vector (float4, unroll 4).
//    Epilogue on warp 0: lanes 0-2 gumbels, lanes 3-4 red-sum+fb+bias,
//    lane 0 argmax + log-softmax -> out[p].
// ---------------------------------------------------------------------------
__global__ void __launch_bounds__(512, 2)
k_fused(const float* __restrict__ input_signal,
        const float* __restrict__ hist,
        const float* __restrict__ W,
        const float* __restrict__ fb_w,
        const float* __restrict__ bias,
        const float* __restrict__ ff_f,
        const float* __restrict__ fb_f,
        float* __restrict__ out) {
    extern __shared__ float4 sv[];        // KV4 float4 = 64160 B
    __shared__ float red[16];

    const int tid = threadIdx.x;

    // ---- Prologue: ff_tr[n,a,b] into smem, flat i = (n*2+a)*2 + b ----
    float* svf = reinterpret_cast<float*>(sv);
    for (int i = tid; i < KLEN; i += 512) {
        int b  = i & 1;
        int na = i >> 1;
        const float* h = hist + na * TAU;
        float s = 0.f;
#pragma unroll
        for (int t = 0; t < TAU; t++)
            s = fmaf(__ldg(h + TAU - 1 - t), __ldg(ff_f + b * TAU + t), s);
        svf[i] = s;
    }
    __syncthreads();

    const int half = tid >> 8;            // 0 -> row 2p, 1 -> row 2p+1
    const int lane = tid & 255;
    const int warp = tid >> 5;
    const int l32  = tid & 31;

    for (int p = blockIdx.x; p < L_TOT; p += GRID) {
        const int row = 2 * p + half;
        const float4* w4 = reinterpret_cast<const float4*>(W) + (size_t)row * KV4;

        float acc = 0.f;
#pragma unroll 4
        for (int i = lane; i < KV4; i += 256) {
            float4 w = __ldg(w4 + i);
            float4 v = sv[i];
            acc = fmaf(w.x, v.x, fmaf(w.y, v.y, fmaf(w.z, v.z, fmaf(w.w, v.w, acc))));
        }
#pragma unroll
        for (int o = 16; o > 0; o >>= 1)
            acc += __shfl_down_sync(0xffffffffu, acc, o);
        if (l32 == 0) red[warp] = acc;
        __syncthreads();

        if (warp == 0) {
            // lanes 0-2: the three gumbel draws (fp64 log chain, in parallel)
            float g = 0.f;
            if (p < N_H && l32 < 3)
                g = gumbel_at(3u * (uint32_t)p + (uint32_t)l32);

            // lanes 3-4: potential for rows 2p / 2p+1 (red-sum + fb_pot + bias)
            float pot = 0.f;
            if (l32 == 3 || l32 == 4) {
                int h2 = l32 - 3;                 // which row of the pair
                int r  = 2 * p + h2;
                float s = 0.f;
#pragma unroll
                for (int w = 0; w < 8; w++) s += red[h2 * 8 + w];
                // fb_tr[N_IN+p, h2, k] from hist (10-tap, two k)
                const float* hh = hist + ((N_IN + p) * 2 + h2) * TAU;
                float f0 = 0.f, f1 = 0.f;
#pragma unroll
                for (int t = 0; t < TAU; t++) {
                    float sp = __ldg(hh + TAU - 1 - t);
                    f0 = fmaf(sp, __ldg(fb_f + t), f0);
                    f1 = fmaf(sp, __ldg(fb_f + TAU + t), f1);
                }
                pot = s + fb_w[r * 2] * f0 + fb_w[r * 2 + 1] * f1 + bias[r];
            }

            float g0 = __shfl_sync(0xffffffffu, g, 0);
            float g1 = __shfl_sync(0xffffffffu, g, 1);
            float g2 = __shfl_sync(0xffffffffu, g, 2);
            float p0 = __shfl_sync(0xffffffffu, pot, 3);
            float p1 = __shfl_sync(0xffffffffu, pot, 4);

            if (l32 == 0) {
                float s0, s1;
                if (p < N_H) {
                    float z0 = g0, z1 = p0 + g1, z2 = p1 + g2;
                    int best = 0; float bv = z0;
                    if (z1 > bv) { bv = z1; best = 1; }
                    if (z2 > bv) {          best = 2; }
                    s0 = (best == 1) ? 1.f : 0.f;
                    s1 = (best == 2) ? 1.f : 0.f;
                } else {
                    int r = N_IN + (p - N_H);
                    s0 = input_signal[r * 2];
                    s1 = input_signal[r * 2 + 1];
                }
                float m   = fmaxf(0.f, fmaxf(p0, p1));
                float lse = m + logf(expf(-m) + expf(p0 - m) + expf(p1 - m));
                out[p] = (1.f - s0 - s1) * (-lse) + s0 * (p0 - lse) + s1 * (p1 - lse);
            }
        }
        __syncthreads();                  // red[] reuse guard
    }
}

// ---------------------------------------------------------------------------
extern "C" void kernel_launch(void* const* d_in, const int* in_sizes, int n_in,
                              void* d_out, int out_size) {
    const float* input_signal = (const float*)d_in[0];
    const float* hist         = (const float*)d_in[1];
    const float* ff_w         = (const float*)d_in[2];
    const float* fb_w         = (const float*)d_in[3];
    const float* bias         = (const float*)d_in[4];
    const float* ff_f         = (const float*)d_in[5];
    const float* fb_f         = (const float*)d_in[6];
    float* out = (float*)d_out;

    (void)in_sizes; (void)n_in; (void)out_size;

    cudaFuncSetAttribute(k_fused, cudaFuncAttributeMaxDynamicSharedMemorySize,
                         KV4 * 16);

    k_fused<<<GRID, 512, KV4 * 16>>>(input_signal, hist, ff_w, fb_w, bias,
                                     ff_f, fb_f, out);
}

// round 5
// speedup vs baseline: 1.2166x; 1.1970x over previous
#include <cuda_runtime.h>
#include <cstdint>

// Problem constants
#define N_IN   1000
#define N_H    3000
#define N_OUT  10
#define N_TOT  4010
#define L_TOT  3010              // output elements / row-pairs
#define TAU    10
#define KLEN   16040             // GEMV reduction length
#define KV4    4010              // KLEN / 4
#define GRID   296               // 2 persistent CTAs / SM
#define FULLM  0xffffffffu

__device__ __align__(16) float g_tr_ff[KLEN];

// ---------------------------------------------------------------------------
// K1: ff transform (hist read ONCE chip-wide), i = (n*2+a)*2 + b
// ---------------------------------------------------------------------------
__global__ void __launch_bounds__(128)
k_transform(const float* __restrict__ hist, const float* __restrict__ ff_f) {
    int i = blockIdx.x * blockDim.x + threadIdx.x;
    if (i >= KLEN) return;
    int b  = i & 1;
    int na = i >> 1;
    const float* h = hist + na * TAU;
    float s = 0.f;
#pragma unroll
    for (int t = 0; t < TAU; t++)
        s = fmaf(__ldg(h + TAU - 1 - t), __ldg(ff_f + b * TAU + t), s);
    g_tr_ff[i] = s;
}

// ---------------------------------------------------------------------------
// Threefry2x32 (partitionable), key (0,1) — verified rel_err 1.5e-7
// ---------------------------------------------------------------------------
__device__ __forceinline__ uint32_t rotl32(uint32_t v, int d) {
    return (v << d) | (v >> (32 - d));
}
__device__ __forceinline__ void threefry2x32_01(uint32_t c0, uint32_t c1,
                                                uint32_t& o0, uint32_t& o1) {
    const uint32_t k0 = 0u, k1 = 1u;
    const uint32_t k2 = k0 ^ k1 ^ 0x1BD11BDAu;
    uint32_t x0 = c0 + k0, x1 = c1 + k1;
#define TF_RND(r) { x0 += x1; x1 = rotl32(x1, (r)) ^ x0; }
    TF_RND(13) TF_RND(15) TF_RND(26) TF_RND(6)   x0 += k1; x1 += k2 + 1u;
    TF_RND(17) TF_RND(29) TF_RND(16) TF_RND(24)  x0 += k2; x1 += k0 + 2u;
    TF_RND(13) TF_RND(15) TF_RND(26) TF_RND(6)   x0 += k0; x1 += k1 + 3u;
    TF_RND(17) TF_RND(29) TF_RND(16) TF_RND(24)  x0 += k1; x1 += k2 + 4u;
    TF_RND(13) TF_RND(15) TF_RND(26) TF_RND(6)   x0 += k2; x1 += k0 + 5u;
#undef TF_RND
    o0 = x0; o1 = x1;
}
__device__ __forceinline__ float gumbel_at(uint32_t f) {
    uint32_t o0, o1;
    threefry2x32_01(0u, f, o0, o1);
    uint32_t bits = o0 ^ o1;
    float uf = __uint_as_float((bits >> 9) | 0x3f800000u) - 1.0f;
    const float tiny = 1.1754943508222875e-38f;
    if (uf < tiny) uf = tiny;
    return (float)(-log(-log((double)uf)));
}

// named-barrier helpers (ids 1-4 = "red[b] ready", 5-8 = "red[b] free")
__device__ __forceinline__ void bar_sync(int id)   {
    asm volatile("bar.sync %0, 512;"   :: "r"(id) : "memory");
}
__device__ __forceinline__ void bar_arrive(int id) {
    asm volatile("bar.arrive %0, 512;" :: "r"(id) : "memory");
}

// ---------------------------------------------------------------------------
// K2: warp-specialized persistent GEMV + epilogue.
//   warps 1-15 (480 thr): stream one 64KB weight row at a time, warp-reduce,
//     publish sums to red[row&3][warp-1], bar.arrive(ready).
//   warp 0: precompute gumbels+fb (overlapped), bar.sync both rows of pair,
//     combine, argmax, log-softmax -> out[p], bar.arrive(free) x2.
// ---------------------------------------------------------------------------
__global__ void __launch_bounds__(512, 2)
k_main(const float* __restrict__ input_signal,
       const float* __restrict__ hist,
       const float* __restrict__ W,
       const float* __restrict__ fb_w,
       const float* __restrict__ bias,
       const float* __restrict__ fb_f,
       float* __restrict__ out) {
    extern __shared__ float4 sv[];        // KV4 float4 = 64160 B
    __shared__ float red[4][16];          // [buf][streamer warp], [15] pad

    const int tid  = threadIdx.x;
    const int warp = tid >> 5;
    const int l32  = tid & 31;

    // prologue: copy transform vector (L2-resident) into smem
    {
        const float4* v4 = reinterpret_cast<const float4*>(g_tr_ff);
        for (int i = tid; i < KV4; i += 512) sv[i] = v4[i];
    }
    __syncthreads();

    if (warp == 0) {
        // ---- epilogue warp ----
#pragma unroll
        for (int b = 0; b < 4; b++) bar_arrive(5 + b);   // prime free buffers

        int cnt = 0;
        for (int p = blockIdx.x; p < L_TOT; p += GRID) {
            const int b0 = cnt & 3, b1 = (cnt + 1) & 3;
            cnt += 2;

            // precompute (overlaps streaming): lanes 0-2 gumbels, 4-5 fb+bias
            float g = 0.f;
            if (p < N_H && l32 < 3)
                g = gumbel_at(3u * (uint32_t)p + (uint32_t)l32);
            float fbp = 0.f;
            if (l32 == 4 || l32 == 5) {
                int h2 = l32 - 4;
                int r  = 2 * p + h2;
                const float* hh = hist + ((N_IN + p) * 2 + h2) * TAU;
                float f0 = 0.f, f1 = 0.f;
#pragma unroll
                for (int t = 0; t < TAU; t++) {
                    float sp = __ldg(hh + TAU - 1 - t);
                    f0 = fmaf(sp, __ldg(fb_f + t),       f0);
                    f1 = fmaf(sp, __ldg(fb_f + TAU + t), f1);
                }
                fbp = fb_w[r * 2] * f0 + fb_w[r * 2 + 1] * f1 + bias[r];
            }

            bar_sync(1 + b0);             // row 2p sums ready
            bar_sync(1 + b1);             // row 2p+1 sums ready

            float v = 0.f;
            if (l32 < 15)                      v = red[b0][l32];
            else if (l32 >= 16 && l32 < 31)    v = red[b1][l32 - 16];
#pragma unroll
            for (int o = 8; o > 0; o >>= 1)
                v += __shfl_down_sync(FULLM, v, o, 16);
            float sum0 = __shfl_sync(FULLM, v, 0);
            float sum1 = __shfl_sync(FULLM, v, 16);

            bar_arrive(5 + b0);           // release buffers for reuse
            bar_arrive(5 + b1);

            float g0  = __shfl_sync(FULLM, g, 0);
            float g1  = __shfl_sync(FULLM, g, 1);
            float g2  = __shfl_sync(FULLM, g, 2);
            float fb0 = __shfl_sync(FULLM, fbp, 4);
            float fb1 = __shfl_sync(FULLM, fbp, 5);

            if (l32 == 0) {
                float p0 = sum0 + fb0, p1 = sum1 + fb1;
                float s0, s1;
                if (p < N_H) {
                    float z0 = g0, z1 = p0 + g1, z2 = p1 + g2;
                    int best = 0; float bv = z0;
                    if (z1 > bv) { bv = z1; best = 1; }
                    if (z2 > bv) {          best = 2; }
                    s0 = (best == 1) ? 1.f : 0.f;
                    s1 = (best == 2) ? 1.f : 0.f;
                } else {
                    int r = N_IN + (p - N_H);
                    s0 = input_signal[r * 2];
                    s1 = input_signal[r * 2 + 1];
                }
                float m   = fmaxf(0.f, fmaxf(p0, p1));
                float lse = m + logf(expf(-m) + expf(p0 - m) + expf(p1 - m));
                out[p] = (1.f - s0 - s1) * (-lse) + s0 * (p0 - lse) + s1 * (p1 - lse);
            }
        }
    } else {
        // ---- streamer warps 1-15 ----
        const int s = tid - 32;           // 0..479
        int cnt = 0;
        for (int p = blockIdx.x; p < L_TOT; p += GRID) {
#pragma unroll
            for (int h = 0; h < 2; h++) {
                const int b = cnt & 3;
                cnt++;
                bar_sync(5 + b);          // buffer free (normally no wait)

                const float4* w4 =
                    reinterpret_cast<const float4*>(W) + (size_t)(2 * p + h) * KV4;
                float acc = 0.f;
#pragma unroll 4
                for (int i = s; i < KV4; i += 480) {
                    float4 w = __ldg(w4 + i);
                    float4 v = sv[i];
                    acc = fmaf(w.x, v.x, fmaf(w.y, v.y,
                          fmaf(w.z, v.z, fmaf(w.w, v.w, acc))));
                }
#pragma unroll
                for (int o = 16; o > 0; o >>= 1)
                    acc += __shfl_down_sync(FULLM, acc, o);
                if (l32 == 0) red[b][warp - 1] = acc;
                __threadfence_block();    // publish before arrive (no implicit fence)
                bar_arrive(1 + b);        // row sums ready
            }
        }
    }
}

// ---------------------------------------------------------------------------
extern "C" void kernel_launch(void* const* d_in, const int* in_sizes, int n_in,
                              void* d_out, int out_size) {
    const float* input_signal = (const float*)d_in[0];
    const float* hist         = (const float*)d_in[1];
    const float* ff_w         = (const float*)d_in[2];
    const float* fb_w         = (const float*)d_in[3];
    const float* bias         = (const float*)d_in[4];
    const float* ff_f         = (const float*)d_in[5];
    const float* fb_f         = (const float*)d_in[6];
    float* out = (float*)d_out;

    (void)in_sizes; (void)n_in; (void)out_size;

    cudaFuncSetAttribute(k_main, cudaFuncAttributeMaxDynamicSharedMemorySize,
                         KV4 * 16);

    k_transform<<<(KLEN + 127) / 128, 128>>>(hist, ff_f);
    k_main<<<GRID, 512, KV4 * 16>>>(input_signal, hist, ff_w, fb_w, bias,
                                    fb_f, out);
}

// round 6
// speedup vs baseline: 1.2518x; 1.0290x over previous
#include <cuda_runtime.h>
#include <cstdint>

// Problem constants
#define N_IN   1000
#define N_H    3000
#define N_OUT  10
#define N_TOT  4010
#define L_TOT  3010              // output elements / row-pairs
#define TAU    10
#define KLEN   16040             // GEMV reduction length
#define KV4    4010              // KLEN / 4
#define GRID   296               // 2 persistent CTAs / SM
#define FULLM  0xffffffffu

__device__ __align__(16) float g_tr_ff[KLEN];

// ---------------------------------------------------------------------------
// K1: ff transform (hist read ONCE chip-wide), i = (n*2+a)*2 + b
// ---------------------------------------------------------------------------
__global__ void __launch_bounds__(128)
k_transform(const float* __restrict__ hist, const float* __restrict__ ff_f) {
    int i = blockIdx.x * blockDim.x + threadIdx.x;
    if (i >= KLEN) return;
    int b  = i & 1;
    int na = i >> 1;
    const float* h = hist + na * TAU;
    float s = 0.f;
#pragma unroll
    for (int t = 0; t < TAU; t++)
        s = fmaf(__ldg(h + TAU - 1 - t), __ldg(ff_f + b * TAU + t), s);
    g_tr_ff[i] = s;
}

// ---------------------------------------------------------------------------
// Threefry2x32 (partitionable), key (0,1) — verified rel_err 1.5e-7
// ---------------------------------------------------------------------------
__device__ __forceinline__ uint32_t rotl32(uint32_t v, int d) {
    return (v << d) | (v >> (32 - d));
}
__device__ __forceinline__ void threefry2x32_01(uint32_t c0, uint32_t c1,
                                                uint32_t& o0, uint32_t& o1) {
    const uint32_t k0 = 0u, k1 = 1u;
    const uint32_t k2 = k0 ^ k1 ^ 0x1BD11BDAu;
    uint32_t x0 = c0 + k0, x1 = c1 + k1;
#define TF_RND(r) { x0 += x1; x1 = rotl32(x1, (r)) ^ x0; }
    TF_RND(13) TF_RND(15) TF_RND(26) TF_RND(6)   x0 += k1; x1 += k2 + 1u;
    TF_RND(17) TF_RND(29) TF_RND(16) TF_RND(24)  x0 += k2; x1 += k0 + 2u;
    TF_RND(13) TF_RND(15) TF_RND(26) TF_RND(6)   x0 += k0; x1 += k1 + 3u;
    TF_RND(17) TF_RND(29) TF_RND(16) TF_RND(24)  x0 += k1; x1 += k2 + 4u;
    TF_RND(13) TF_RND(15) TF_RND(26) TF_RND(6)   x0 += k2; x1 += k0 + 5u;
#undef TF_RND
    o0 = x0; o1 = x1;
}
__device__ __forceinline__ float gumbel_at(uint32_t f) {
    uint32_t o0, o1;
    threefry2x32_01(0u, f, o0, o1);
    uint32_t bits = o0 ^ o1;
    float uf = __uint_as_float((bits >> 9) | 0x3f800000u) - 1.0f;
    const float tiny = 1.1754943508222875e-38f;
    if (uf < tiny) uf = tiny;
    return (float)(-log(-log((double)uf)));
}

// named barriers: ids 1-2 = "pair buffer b ready", 3-4 = "pair buffer b free"
__device__ __forceinline__ void bar_sync(int id)   {
    asm volatile("bar.sync %0, 512;"   :: "r"(id) : "memory");
}
__device__ __forceinline__ void bar_arrive(int id) {
    asm volatile("bar.arrive %0, 512;" :: "r"(id) : "memory");
}

// ---------------------------------------------------------------------------
// K2: warp-specialized persistent GEMV + epilogue, PAIR-wise streaming.
//   warps 1-15 (480 thr): stream BOTH 64KB rows of pair p together
//     (2 accumulators, boundary drain once per 128KB), publish to
//     red[b][2][16], bar.arrive(ready b).
//   warp 0: precompute gumbels+fb overlapped, bar.sync(ready b), combine,
//     argmax + log-softmax -> out[p], bar.arrive(free b).
// ---------------------------------------------------------------------------
__global__ void __launch_bounds__(512, 2)
k_main(const float* __restrict__ input_signal,
       const float* __restrict__ hist,
       const float* __restrict__ W,
       const float* __restrict__ fb_w,
       const float* __restrict__ bias,
       const float* __restrict__ fb_f,
       float* __restrict__ out) {
    extern __shared__ float4 sv[];        // KV4 float4 = 64160 B
    __shared__ float red[2][2][16];       // [buf][row of pair][streamer warp]

    const int tid  = threadIdx.x;
    const int warp = tid >> 5;
    const int l32  = tid & 31;

    // prologue: copy transform vector (L2-resident) into smem
    {
        const float4* v4 = reinterpret_cast<const float4*>(g_tr_ff);
        for (int i = tid; i < KV4; i += 512) sv[i] = v4[i];
    }
    __syncthreads();

    if (warp == 0) {
        // ---- epilogue warp ----
        bar_arrive(3); bar_arrive(4);     // prime free buffers

        int cnt = 0;
        for (int p = blockIdx.x; p < L_TOT; p += GRID) {
            const int b = cnt & 1;
            cnt++;

            // precompute (overlaps streaming): lanes 0-2 gumbels, 4-5 fb+bias
            float g = 0.f;
            if (p < N_H && l32 < 3)
                g = gumbel_at(3u * (uint32_t)p + (uint32_t)l32);
            float fbp = 0.f;
            if (l32 == 4 || l32 == 5) {
                int h2 = l32 - 4;
                int r  = 2 * p + h2;
                const float* hh = hist + ((N_IN + p) * 2 + h2) * TAU;
                float f0 = 0.f, f1 = 0.f;
#pragma unroll
                for (int t = 0; t < TAU; t++) {
                    float sp = __ldg(hh + TAU - 1 - t);
                    f0 = fmaf(sp, __ldg(fb_f + t),       f0);
                    f1 = fmaf(sp, __ldg(fb_f + TAU + t), f1);
                }
                fbp = fb_w[r * 2] * f0 + fb_w[r * 2 + 1] * f1 + bias[r];
            }

            bar_sync(1 + b);              // pair sums ready

            float v = 0.f;
            if (l32 < 15)                      v = red[b][0][l32];
            else if (l32 >= 16 && l32 < 31)    v = red[b][1][l32 - 16];
#pragma unroll
            for (int o = 8; o > 0; o >>= 1)
                v += __shfl_down_sync(FULLM, v, o, 16);
            float sum0 = __shfl_sync(FULLM, v, 0);
            float sum1 = __shfl_sync(FULLM, v, 16);

            bar_arrive(3 + b);            // release buffer

            float g0  = __shfl_sync(FULLM, g, 0);
            float g1  = __shfl_sync(FULLM, g, 1);
            float g2  = __shfl_sync(FULLM, g, 2);
            float fb0 = __shfl_sync(FULLM, fbp, 4);
            float fb1 = __shfl_sync(FULLM, fbp, 5);

            if (l32 == 0) {
                float p0 = sum0 + fb0, p1 = sum1 + fb1;
                float s0, s1;
                if (p < N_H) {
                    float z0 = g0, z1 = p0 + g1, z2 = p1 + g2;
                    int best = 0; float bv = z0;
                    if (z1 > bv) { bv = z1; best = 1; }
                    if (z2 > bv) {          best = 2; }
                    s0 = (best == 1) ? 1.f : 0.f;
                    s1 = (best == 2) ? 1.f : 0.f;
                } else {
                    int r = N_IN + (p - N_H);
                    s0 = input_signal[r * 2];
                    s1 = input_signal[r * 2 + 1];
                }
                float m   = fmaxf(0.f, fmaxf(p0, p1));
                float lse = m + logf(expf(-m) + expf(p0 - m) + expf(p1 - m));
                out[p] = (1.f - s0 - s1) * (-lse) + s0 * (p0 - lse) + s1 * (p1 - lse);
            }
        }
    } else {
        // ---- streamer warps 1-15: both rows of the pair together ----
        const int s = tid - 32;           // 0..479
        int cnt = 0;
        for (int p = blockIdx.x; p < L_TOT; p += GRID) {
            const int b = cnt & 1;
            cnt++;
            bar_sync(3 + b);              // buffer free (normally no wait)

            const float4* w0 =
                reinterpret_cast<const float4*>(W) + (size_t)(2 * p) * KV4;
            const float4* w1 = w0 + KV4;

            float acc0 = 0.f, acc1 = 0.f;
#pragma unroll 2
            for (int i = s; i < KV4; i += 480) {
                float4 a = __ldg(w0 + i);
                float4 c = __ldg(w1 + i);
                float4 v = sv[i];
                acc0 = fmaf(a.x, v.x, fmaf(a.y, v.y,
                       fmaf(a.z, v.z, fmaf(a.w, v.w, acc0))));
                acc1 = fmaf(c.x, v.x, fmaf(c.y, v.y,
                       fmaf(c.z, v.z, fmaf(c.w, v.w, acc1))));
            }
#pragma unroll
            for (int o = 16; o > 0; o >>= 1) {
                acc0 += __shfl_down_sync(FULLM, acc0, o);
                acc1 += __shfl_down_sync(FULLM, acc1, o);
            }
            if (l32 == 0) {
                red[b][0][warp - 1] = acc0;
                red[b][1][warp - 1] = acc1;
            }
            __threadfence_block();        // publish before arrive
            bar_arrive(1 + b);            // pair sums ready
        }
    }
}

// ---------------------------------------------------------------------------
extern "C" void kernel_launch(void* const* d_in, const int* in_sizes, int n_in,
                              void* d_out, int out_size) {
    const float* input_signal = (const float*)d_in[0];
    const float* hist         = (const float*)d_in[1];
    const float* ff_w         = (const float*)d_in[2];
    const float* fb_w         = (const float*)d_in[3];
    const float* bias         = (const float*)d_in[4];
    const float* ff_f         = (const float*)d_in[5];
    const float* fb_f         = (const float*)d_in[6];
    float* out = (float*)d_out;

    (void)in_sizes; (void)n_in; (void)out_size;

    cudaFuncSetAttribute(k_main, cudaFuncAttributeMaxDynamicSharedMemorySize,
                         KV4 * 16);

    k_transform<<<(KLEN + 127) / 128, 128>>>(hist, ff_f);
    k_main<<<GRID, 512, KV4 * 16>>>(input_signal, hist, ff_w, fb_w, bias,
                                    fb_f, out);
}

// round 8
// speedup vs baseline: 1.2898x; 1.0303x over previous
#include <cuda_runtime.h>
#include <cstdint>

// Problem constants
#define N_IN   1000
#define N_H    3000
#define N_OUT  10
#define N_TOT  4010
#define L_TOT  3010              // output elements / row-pairs
#define TAU    10
#define KLEN   16040             // GEMV reduction length
#define KV4    4010              // KLEN / 4
#define GRID   444               // 3 persistent CTAs / SM on 148 SMs
#define NTHR   384               // 1 epilogue warp + 11 streamer warps
#define NSTR   352               // streamer lanes
#define FULLM  0xffffffffu

__device__ __align__(16) float g_tr_ff[KLEN];

// ---------------------------------------------------------------------------
// K1: ff transform (hist read ONCE chip-wide), i = (n*2+a)*2 + b
// ---------------------------------------------------------------------------
__global__ void __launch_bounds__(128)
k_transform(const float* __restrict__ hist, const float* __restrict__ ff_f) {
    int i = blockIdx.x * blockDim.x + threadIdx.x;
    if (i >= KLEN) return;
    int b  = i & 1;
    int na = i >> 1;
    const float* h = hist + na * TAU;
    float s = 0.f;
#pragma unroll
    for (int t = 0; t < TAU; t++)
        s = fmaf(__ldg(h + TAU - 1 - t), __ldg(ff_f + b * TAU + t), s);
    g_tr_ff[i] = s;
}

// ---------------------------------------------------------------------------
// Threefry2x32 (partitionable), key (0,1) — verified rel_err 1.5e-7
// ---------------------------------------------------------------------------
__device__ __forceinline__ uint32_t rotl32(uint32_t v, int d) {
    return (v << d) | (v >> (32 - d));
}
__device__ __forceinline__ void threefry2x32_01(uint32_t c0, uint32_t c1,
                                                uint32_t& o0, uint32_t& o1) {
    const uint32_t k0 = 0u, k1 = 1u;
    const uint32_t k2 = k0 ^ k1 ^ 0x1BD11BDAu;
    uint32_t x0 = c0 + k0, x1 = c1 + k1;
#define TF_RND(r) { x0 += x1; x1 = rotl32(x1, (r)) ^ x0; }
    TF_RND(13) TF_RND(15) TF_RND(26) TF_RND(6)   x0 += k1; x1 += k2 + 1u;
    TF_RND(17) TF_RND(29) TF_RND(16) TF_RND(24)  x0 += k2; x1 += k0 + 2u;
    TF_RND(13) TF_RND(15) TF_RND(26) TF_RND(6)   x0 += k0; x1 += k1 + 3u;
    TF_RND(17) TF_RND(29) TF_RND(16) TF_RND(24)  x0 += k1; x1 += k2 + 4u;
    TF_RND(13) TF_RND(15) TF_RND(26) TF_RND(6)   x0 += k2; x1 += k0 + 5u;
#undef TF_RND
    o0 = x0; o1 = x1;
}
__device__ __forceinline__ float gumbel_at(uint32_t f) {
    uint32_t o0, o1;
    threefry2x32_01(0u, f, o0, o1);
    uint32_t bits = o0 ^ o1;
    float uf = __uint_as_float((bits >> 9) | 0x3f800000u) - 1.0f;
    const float tiny = 1.1754943508222875e-38f;
    if (uf < tiny) uf = tiny;
    return (float)(-log(-log((double)uf)));
}

// named barriers: ids 1-2 = "pair buffer b ready", 3-4 = "pair buffer b free"
__device__ __forceinline__ void bar_sync(int id)   {
    asm volatile("bar.sync %0, 384;"   :: "r"(id) : "memory");
}
__device__ __forceinline__ void bar_arrive(int id) {
    asm volatile("bar.arrive %0, 384;" :: "r"(id) : "memory");
}

// ---------------------------------------------------------------------------
// K2: warp-specialized persistent GEMV + epilogue, PAIR-wise streaming.
//   3 CTAs/SM (384 thr each): finer tail (ceil 7 vs avg 6.78 pairs) and
//   3-way boundary de-phasing per SM.
//   warps 1-11 (352 thr): stream BOTH 64KB rows of pair p together,
//     publish to red[b][2][16], bar.arrive(ready b).
//   warp 0: precompute gumbels+fb overlapped, bar.sync(ready b), combine,
//     argmax + log-softmax -> out[p], bar.arrive(free b).
// ---------------------------------------------------------------------------
__global__ void __launch_bounds__(NTHR, 3)
k_main(const float* __restrict__ input_signal,
       const float* __restrict__ hist,
       const float* __restrict__ W,
       const float* __restrict__ fb_w,
       const float* __restrict__ bias,
       const float* __restrict__ fb_f,
       float* __restrict__ out) {
    extern __shared__ float4 sv[];        // KV4 float4 = 64160 B
    __shared__ float red[2][2][16];       // [buf][row of pair][streamer warp]

    const int tid  = threadIdx.x;
    const int warp = tid >> 5;
    const int l32  = tid & 31;

    // prologue: copy transform vector (L2-resident) into smem
    {
        const float4* v4 = reinterpret_cast<const float4*>(g_tr_ff);
        for (int i = tid; i < KV4; i += NTHR) sv[i] = v4[i];
    }
    __syncthreads();

    if (warp == 0) {
        // ---- epilogue warp ----
        bar_arrive(3); bar_arrive(4);     // prime free buffers

        int cnt = 0;
        for (int p = blockIdx.x; p < L_TOT; p += GRID) {
            const int b = cnt & 1;
            cnt++;

            // precompute (overlaps streaming): lanes 0-2 gumbels, 4-5 fb+bias
            float g = 0.f;
            if (p < N_H && l32 < 3)
                g = gumbel_at(3u * (uint32_t)p + (uint32_t)l32);
            float fbp = 0.f;
            if (l32 == 4 || l32 == 5) {
                int h2 = l32 - 4;
                int r  = 2 * p + h2;
                const float* hh = hist + ((N_IN + p) * 2 + h2) * TAU;
                float f0 = 0.f, f1 = 0.f;
#pragma unroll
                for (int t = 0; t < TAU; t++) {
                    float sp = __ldg(hh + TAU - 1 - t);
                    f0 = fmaf(sp, __ldg(fb_f + t),       f0);
                    f1 = fmaf(sp, __ldg(fb_f + TAU + t), f1);
                }
                fbp = fb_w[r * 2] * f0 + fb_w[r * 2 + 1] * f1 + bias[r];
            }

            bar_sync(1 + b);              // pair sums ready

            float v = 0.f;
            if (l32 < 11)                      v = red[b][0][l32];
            else if (l32 >= 16 && l32 < 27)    v = red[b][1][l32 - 16];
#pragma unroll
            for (int o = 8; o > 0; o >>= 1)
                v += __shfl_down_sync(FULLM, v, o, 16);
            float sum0 = __shfl_sync(FULLM, v, 0);
            float sum1 = __shfl_sync(FULLM, v, 16);

            bar_arrive(3 + b);            // release buffer

            float g0  = __shfl_sync(FULLM, g, 0);
            float g1  = __shfl_sync(FULLM, g, 1);
            float g2  = __shfl_sync(FULLM, g, 2);
            float fb0 = __shfl_sync(FULLM, fbp, 4);
            float fb1 = __shfl_sync(FULLM, fbp, 5);

            if (l32 == 0) {
                float p0 = sum0 + fb0, p1 = sum1 + fb1;
                float s0, s1;
                if (p < N_H) {
                    float z0 = g0, z1 = p0 + g1, z2 = p1 + g2;
                    int best = 0; float bv = z0;
                    if (z1 > bv) { bv = z1; best = 1; }
                    if (z2 > bv) {          best = 2; }
                    s0 = (best == 1) ? 1.f : 0.f;
                    s1 = (best == 2) ? 1.f : 0.f;
                } else {
                    int r = N_IN + (p - N_H);
                    s0 = input_signal[r * 2];
                    s1 = input_signal[r * 2 + 1];
                }
                float m   = fmaxf(0.f, fmaxf(p0, p1));
                float lse = m + logf(expf(-m) + expf(p0 - m) + expf(p1 - m));
                out[p] = (1.f - s0 - s1) * (-lse) + s0 * (p0 - lse) + s1 * (p1 - lse);
            }
        }
    } else {
        // ---- streamer warps 1-11: both rows of the pair together ----
        const int s = tid - 32;           // 0..351
        int cnt = 0;
        for (int p = blockIdx.x; p < L_TOT; p += GRID) {
            const int b = cnt & 1;
            cnt++;
            bar_sync(3 + b);              // buffer free (normally no wait)

            const float4* w0 =
                reinterpret_cast<const float4*>(W) + (size_t)(2 * p) * KV4;
            const float4* w1 = w0 + KV4;

            float acc0 = 0.f, acc1 = 0.f;
#pragma unroll 2
            for (int i = s; i < KV4; i += NSTR) {
                float4 a = __ldg(w0 + i);
                float4 c = __ldg(w1 + i);
                float4 v = sv[i];
                acc0 = fmaf(a.x, v.x, fmaf(a.y, v.y,
                       fmaf(a.z, v.z, fmaf(a.w, v.w, acc0))));
                acc1 = fmaf(c.x, v.x, fmaf(c.y, v.y,
                       fmaf(c.z, v.z, fmaf(c.w, v.w, acc1))));
            }
#pragma unroll
            for (int o = 16; o > 0; o >>= 1) {
                acc0 += __shfl_down_sync(FULLM, acc0, o);
                acc1 += __shfl_down_sync(FULLM, acc1, o);
            }
            if (l32 == 0) {
                red[b][0][warp - 1] = acc0;
                red[b][1][warp - 1] = acc1;
            }
            __threadfence_block();        // publish before arrive
            bar_arrive(1 + b);            // pair sums ready
        }
    }
}

// ---------------------------------------------------------------------------
extern "C" void kernel_launch(void* const* d_in, const int* in_sizes, int n_in,
                              void* d_out, int out_size) {
    const float* input_signal = (const float*)d_in[0];
    const float* hist         = (const float*)d_in[1];
    const float* ff_w         = (const float*)d_in[2];
    const float* fb_w         = (const float*)d_in[3];
    const float* bias         = (const float*)d_in[4];
    const float* ff_f         = (const float*)d_in[5];
    const float* fb_f         = (const float*)d_in[6];
    float* out = (float*)d_out;

    (void)in_sizes; (void)n_in; (void)out_size;

    cudaFuncSetAttribute(k_main, cudaFuncAttributeMaxDynamicSharedMemorySize,
                         KV4 * 16);

    k_transform<<<(KLEN + 127) / 128, 128>>>(hist, ff_f);
    k_main<<<GRID, NTHR, KV4 * 16>>>(input_signal, hist, ff_w, fb_w, bias,
                                     fb_f, out);
}